// round 13
// baseline (speedup 1.0000x reference)
#include <cuda_runtime.h>
#include <cstdint>

// x: [64,1,512,512] f32; kernels: [5,1,3,3]; biases: [5]
// conv VALID -> [64,5,510,510]; +bias; maxpool2x2 -> [64,5,255,255]; relu.
//
// Tensor-core (tf32 mma.sync m16n8k8) version. GEMM mapping per warp:
//   A [16x8]  = weights: row = channel (0..4 real), col = tap (k slice)
//   B [8x8]   = patch:   row = tap, col = conv-x (8 consecutive x)
//   C [16x8]  = conv:    row = channel, col = conv-x
// C-fragment: lane holds cols 2t,2t+1 (t=lane%4) of row lane/4 -> the
// horizontal pool pair is IN-LANE. Two row-MMAs (y, y+1) -> vertical pool
// in-lane. K=9 = two k8 slices (slice2 carries only tap 8).
// Block: 256 thr = 8 warps; warp w covers conv-x 8w..8w+7 (4 pooled x),
// loops 16 pooled y. Block tile: 32 pooled x, 16 pooled y.

#define INW 512
#define POW 255
#define TSTR 68            // tile row stride (floats)
#define TROWS 34           // 2*16 + 2
#define NLD (TROWS * 33)   // float2 loads per tile = 1122

__device__ __forceinline__ uint32_t f2tf32(float f) {
    uint32_t r;
    asm("cvt.rna.tf32.f32 %0, %1;" : "=r"(r) : "f"(f));
    return r;
}

__device__ __forceinline__ void mma_tf32(float& c0, float& c1, float& c2, float& c3,
                                         uint32_t a0, uint32_t a1, uint32_t a2, uint32_t a3,
                                         uint32_t b0, uint32_t b1) {
    asm("mma.sync.aligned.m16n8k8.row.col.f32.tf32.tf32.f32 "
        "{%0,%1,%2,%3}, {%4,%5,%6,%7}, {%8,%9}, {%0,%1,%2,%3};"
        : "+f"(c0), "+f"(c1), "+f"(c2), "+f"(c3)
        : "r"(a0), "r"(a1), "r"(a2), "r"(a3), "r"(b0), "r"(b1));
}

__global__ __launch_bounds__(256, 6)
void fused_conv_bias_pool_relu_tc(const float* __restrict__ x,
                                  const float* __restrict__ w,
                                  const float* __restrict__ b,
                                  float* __restrict__ out)
{
    __shared__ float tile[TROWS * TSTR];

    const int tid  = threadIdx.x;
    const int lane = tid & 31;
    const int wrp  = tid >> 5;
    const int n    = blockIdx.z;

    // ---- A fragments (weights) + bias: built once, reused all iterations.
    // tap t -> (ky,kx) = (t/3, t%3); taps 0..7 slice1, tap 8 slice2.
    const int ch = lane >> 2;          // C/A row (channel); 5..7 unused
    const int t  = lane & 3;
    const bool chv = (ch < 5);
    uint32_t a0 = 0, a2 = 0, a20 = 0;  // a1 = a3 = 0 (rows 8..15 zero)
    float bias = 0.0f;
    if (chv) {
        a0 = f2tf32(w[ch * 9 + t]);               // taps 0..3
        a2 = f2tf32(w[ch * 9 + t + 4]);           // taps 4..7
        if (t == 0) a20 = f2tf32(w[ch * 9 + 8]);  // tap 8 (slice2 col 0)
        bias = b[ch];
    }

    // ---- Cooperative tile load: conv rows [32*by, 32*by+33],
    //      conv cols [64*bx, 64*bx+65]; clamp -> 0 (masked outputs only).
    const float* __restrict__ xn = x + (size_t)n * INW * INW;
    const int ix0 = 64 * blockIdx.x;
    const int iy0 = 32 * blockIdx.y;
    for (int i = tid; i < NLD; i += 256) {
        const int r  = i / 33;
        const int c2 = i - r * 33;
        const int gy = iy0 + r;
        const int gx = ix0 + 2 * c2;
        float2 v;
        if (gy < INW && gx + 1 < INW) {
            v = *reinterpret_cast<const float2*>(xn + (size_t)gy * INW + gx);
        } else {
            v.x = (gy < INW && gx < INW) ? xn[(size_t)gy * INW + gx] : 0.0f;
            v.y = 0.0f;
        }
        tile[r * TSTR + 2 * c2]     = v.x;
        tile[r * TSTR + 2 * c2 + 1] = v.y;
    }
    __syncthreads();

    // ---- Per-lane B-fragment source offsets (float indices into tile).
    // B col nn = lane>>2 = conv-x offset; b0 = tap t, b1 = tap t+4.
    const int nn   = lane >> 2;
    const int colA = 8 * wrp + nn;
    const int off0 = (t / 3) * TSTR + colA + (t % 3);
    const int off1 = ((t + 4) / 3) * TSTR + colA + ((t + 4) % 3);
    const int off2 = 2 * TSTR + colA + 2;          // tap 8 (t==0 lanes)

    // Output coords for this lane (C fragment: row=ch, cols 2t,2t+1).
    const int px = 32 * blockIdx.x + 4 * wrp + t;  // pooled x
    const bool store_ok = chv && (px < POW);
    const int py0 = 16 * blockIdx.y;
    // 64*5*255*255 < 2^31 -> 32-bit indexing.
    const int obase = ((n * 5 + ch) * POW) * POW + px;

    #pragma unroll 4
    for (int i = 0; i < 16; i++) {
        const float* base0 = &tile[(2 * i) * TSTR];      // conv row y
        const float* base1 = base0 + TSTR;               // conv row y+1

        // conv row y
        float c0 = bias, c1 = bias, c2 = 0.0f, c3 = 0.0f;
        {
            uint32_t b0 = f2tf32(base0[off0]);
            uint32_t b1 = f2tf32(base0[off1]);
            mma_tf32(c0, c1, c2, c3, a0, 0u, a2, 0u, b0, b1);
            uint32_t b2 = (t == 0) ? f2tf32(base0[off2]) : 0u;
            mma_tf32(c0, c1, c2, c3, a20, 0u, 0u, 0u, b2, 0u);
        }
        // conv row y+1
        float d0 = bias, d1 = bias, d2 = 0.0f, d3 = 0.0f;
        {
            uint32_t b0 = f2tf32(base1[off0]);
            uint32_t b1 = f2tf32(base1[off1]);
            mma_tf32(d0, d1, d2, d3, a0, 0u, a2, 0u, b0, b1);
            uint32_t b2 = (t == 0) ? f2tf32(base1[off2]) : 0u;
            mma_tf32(d0, d1, d2, d3, a20, 0u, 0u, 0u, b2, 0u);
        }

        // 2x2 max pool (in-lane) + ReLU.
        const float m = fmaxf(fmaxf(fmaxf(c0, c1), fmaxf(d0, d1)), 0.0f);
        const int py = py0 + i;
        if (store_ok && py < POW) out[obase + py * POW] = m;
    }
}

extern "C" void kernel_launch(void* const* d_in, const int* in_sizes, int n_in,
                              void* d_out, int out_size)
{
    const float* x = (const float*)d_in[0];
    const float* w = (const float*)d_in[1];
    const float* b = (const float*)d_in[2];
    float* out = (float*)d_out;

    dim3 block(256, 1, 1);             // 8 warps
    dim3 grid(8, 16, 64);              // 32 px x 16 py per block, batch
    fused_conv_bias_pool_relu_tc<<<grid, block>>>(x, w, b, out);
}

// round 14
// speedup vs baseline: 1.3243x; 1.3243x over previous
#include <cuda_runtime.h>
#include <cstdint>

// x: [64,1,512,512] f32; kernels: [5,1,3,3]; biases: [5]
// conv VALID -> [64,5,510,510]; +bias; maxpool2x2 -> [64,5,255,255]; relu.
//
// tf32 mma.sync m16n8k8, roles TRANSPOSED vs R13:
//   A [16x8] = activations (row r <-> conv-x = cb+2r, row r+8 <-> cb+2r+1)
//   B [8x8]  = weights, col = channel  (LOOP-INVARIANT registers)
//   C [16x8] = conv out: lane(g,t) holds C[g][2t],C[g][2t+1],C[g+8][2t],C[g+8][2t+1]
//            = x-pool pair (c0,c2)/(c1,c3) IN-LANE, channels 2t / 2t+1.
// K=9 as two k8 slices (slice2 = tap8 in k-col 0 only).
// Tile is PRE-CONVERTED to tf32 bits at load -> zero cvt in the main loop.
// Block: 8 warps; warp w covers pooled-x [8w,8w+8); loop over 16 pooled rows.
// Block tile: 64 pooled x, 16 pooled y. Grid (4,16,64).

#define INW 512
#define POW 255
#define TSTR 132            // tile row stride (tf32 words)
#define TROWS 34            // 2*16 + 2 conv rows
#define TCOL2 65            // float2 loads per row (130 cols)
#define NLD (TROWS * TCOL2) // 2210

__device__ __forceinline__ uint32_t f2tf32(float f) {
    uint32_t r;
    asm("cvt.rna.tf32.f32 %0, %1;" : "=r"(r) : "f"(f));
    return r;
}

__device__ __forceinline__ void mma_tf32(float& c0, float& c1, float& c2, float& c3,
                                         uint32_t a0, uint32_t a1, uint32_t a2, uint32_t a3,
                                         uint32_t b0, uint32_t b1) {
    asm("mma.sync.aligned.m16n8k8.row.col.f32.tf32.tf32.f32 "
        "{%0,%1,%2,%3}, {%4,%5,%6,%7}, {%8,%9}, {%0,%1,%2,%3};"
        : "+f"(c0), "+f"(c1), "+f"(c2), "+f"(c3)
        : "r"(a0), "r"(a1), "r"(a2), "r"(a3), "r"(b0), "r"(b1));
}

__global__ __launch_bounds__(256, 5)
void fused_conv_bias_pool_relu_tc(const float* __restrict__ x,
                                  const float* __restrict__ w,
                                  const float* __restrict__ b,
                                  float* __restrict__ out)
{
    __shared__ uint32_t tile[TROWS * TSTR];   // tf32 bits

    const int tid  = threadIdx.x;
    const int lane = tid & 31;
    const int wrp  = tid >> 5;
    const int n    = blockIdx.z;
    const int g    = lane >> 2;     // A-row group / B-col (channel)
    const int t    = lane & 3;      // k-group

    // ---- Loop-invariant weight (B) fragments. B[tap][ch] = w[ch*9+tap].
    // b0 = B[t][g], b1 = B[t+4][g]; slice2: only k=0 row nonzero (tap 8).
    uint32_t wb0 = 0, wb1 = 0, wb8 = 0;
    if (g < 5) {
        wb0 = f2tf32(w[g * 9 + t]);
        wb1 = f2tf32(w[g * 9 + t + 4]);
        if (t == 0) wb8 = f2tf32(w[g * 9 + 8]);
    }
    // Lane's output channels (from C layout): 2t and 2t+1.
    const int ch0 = 2 * t, ch1 = 2 * t + 1;
    const float bias0 = (ch0 < 5) ? b[ch0] : 0.0f;
    const float bias1 = (ch1 < 5) ? b[ch1] : 0.0f;

    // ---- Tile load with tf32 pre-conversion.
    // conv rows [32*by, 32*by+33], conv cols [128*bx, 128*bx+129]; pad 0.
    const float* __restrict__ xn = x + (size_t)n * INW * INW;
    const int ix0 = 128 * blockIdx.x;
    const int iy0 = 32 * blockIdx.y;
    for (int i = tid; i < NLD; i += 256) {
        const int r  = i / TCOL2;
        const int c2 = i - r * TCOL2;
        const int gy = iy0 + r;
        const int gx = ix0 + 2 * c2;
        float2 v;
        if (gy < INW && gx + 1 < INW) {
            v = *reinterpret_cast<const float2*>(xn + (size_t)gy * INW + gx);
        } else {
            v.x = (gy < INW && gx < INW) ? xn[(size_t)gy * INW + gx] : 0.0f;
            v.y = 0.0f;
        }
        tile[r * TSTR + 2 * c2]     = f2tf32(v.x);
        tile[r * TSTR + 2 * c2 + 1] = f2tf32(v.y);
    }
    __syncthreads();

    // ---- Per-lane A-fragment offsets (words into tile, relative to conv row y).
    // A[g][k]   = in[y + k/3][cb + 2g + k%3],  A[g+8][k] = same row, col+1.
    const int cb   = 16 * wrp;                  // conv-x local base for warp
    const int o_a0 = (t / 3) * TSTR + cb + 2 * g + (t % 3);         // A[g][t]
    const int o_a2 = ((t + 4) / 3) * TSTR + cb + 2 * g + ((t + 4) % 3); // A[g][t+4]
    const int o_s0 = 2 * TSTR + cb + 2 * g + 2;                     // A[g][8]

    // ---- Output coords.
    const int px = 64 * blockIdx.x + 8 * wrp + g;    // pooled x
    const int py0 = 16 * blockIdx.y;
    const bool pxok = (px < POW);
    const bool ok0 = pxok && (ch0 < 5);
    const bool ok1 = pxok && (ch1 < 5);
    // 64*5*255*255 < 2^31 -> 32-bit indexing.
    const int ob0 = ((n * 5 + ch0) * POW) * POW + px;
    const int ob1 = ((n * 5 + ch1) * POW) * POW + px;

    #pragma unroll 4
    for (int i = 0; i < 16; i++) {
        const uint32_t* ry = &tile[(2 * i) * TSTR];   // conv row y = 2*(py0+?) local
        const uint32_t* rz = ry + TSTR;               // conv row y+1

        // conv row y
        float c0 = bias0, c1 = bias1, c2f = bias0, c3f = bias1;
        {
            uint32_t a0 = ry[o_a0], a1 = ry[o_a0 + 1];
            uint32_t a2 = ry[o_a2], a3 = ry[o_a2 + 1];
            mma_tf32(c0, c1, c2f, c3f, a0, a1, a2, a3, wb0, wb1);
            uint32_t s0 = (t == 0) ? ry[o_s0]     : 0u;
            uint32_t s1 = (t == 0) ? ry[o_s0 + 1] : 0u;
            mma_tf32(c0, c1, c2f, c3f, s0, s1, 0u, 0u, wb8, 0u);
        }
        // conv row y+1
        float d0 = bias0, d1 = bias1, d2f = bias0, d3f = bias1;
        {
            uint32_t a0 = rz[o_a0], a1 = rz[o_a0 + 1];
            uint32_t a2 = rz[o_a2], a3 = rz[o_a2 + 1];
            mma_tf32(d0, d1, d2f, d3f, a0, a1, a2, a3, wb0, wb1);
            uint32_t s0 = (t == 0) ? rz[o_s0]     : 0u;
            uint32_t s1 = (t == 0) ? rz[o_s0 + 1] : 0u;
            mma_tf32(d0, d1, d2f, d3f, s0, s1, 0u, 0u, wb8, 0u);
        }

        // Pool: horizontal pair in-lane (c0 vs c2f = x 2px, 2px+1),
        // vertical = rows y vs y+1. Then ReLU.
        const float m0 = fmaxf(fmaxf(fmaxf(c0, c2f), fmaxf(d0, d2f)), 0.0f);
        const float m1 = fmaxf(fmaxf(fmaxf(c1, c3f), fmaxf(d1, d3f)), 0.0f);

        const int py = py0 + i;
        if (py < POW) {
            if (ok0) out[ob0 + py * POW] = m0;
            if (ok1) out[ob1 + py * POW] = m1;
        }
    }
}

extern "C" void kernel_launch(void* const* d_in, const int* in_sizes, int n_in,
                              void* d_out, int out_size)
{
    const float* x = (const float*)d_in[0];
    const float* w = (const float*)d_in[1];
    const float* b = (const float*)d_in[2];
    float* out = (float*)d_out;

    dim3 block(256, 1, 1);             // 8 warps
    dim3 grid(4, 16, 64);              // 64 px x 16 py per block, batch
    fused_conv_bias_pool_relu_tc<<<grid, block>>>(x, w, b, out);
}

// round 16
// speedup vs baseline: 2.2301x; 1.6839x over previous
#include <cuda_runtime.h>
#include <cuda_fp16.h>
#include <cstdint>

// x: [64,1,512,512] f32; kernels: [5,1,3,3]; biases: [5]
// conv VALID -> [64,5,510,510]; +bias; maxpool2x2 -> [64,5,255,255]; relu.
//
// R11 skeleton (direct LDG patch, 1 pooled output x 5ch per thread) with the
// conv arithmetic in HFMA2: half2 lanes = the two horizontal conv positions
// (dx=0,1) of the pooled output; vertical pair = two half2 accumulators.
// 90 HFMA2 replaces 180 FFMA (same rt=2 pipe -> half the fma-pipe time).
// fp32->fp16 conversion in-register (8 cvt); weights {w,w} half2 in shared.

#define TX 32
#define TY 8
#define NTHR (TX * TY)
#define INW 512
#define POW 255

__device__ __forceinline__ uint32_t prmt5432(uint32_t a, uint32_t b) {
    uint32_t d;
    asm("prmt.b32 %0, %1, %2, 0x5432;" : "=r"(d) : "r"(a), "r"(b));
    return d;  // bytes {a.b2,a.b3,b.b0,b.b1} = half2 {a.hi, b.lo}
}
__device__ __forceinline__ uint32_t h2_bits(__half2 h) {
    return *reinterpret_cast<uint32_t*>(&h);
}
__device__ __forceinline__ __half2 bits_h2(uint32_t u) {
    return *reinterpret_cast<__half2*>(&u);
}

__global__ __launch_bounds__(NTHR, 7)
void fused_conv_bias_pool_relu_h2(const float* __restrict__ x,
                                  const float* __restrict__ w,
                                  const float* __restrict__ b,
                                  float* __restrict__ out)
{
    // Per channel: words 0..8 = {w,w} taps 0..8, word 9 = {bias,bias},
    // words 10,11 = pad (16B alignment of every channel row).
    __shared__ uint32_t sWH[5][12];

    const int tx  = threadIdx.x;
    const int ty  = threadIdx.y;
    const int tid = ty * TX + tx;

    if (tid < 50) {
        const int ch = tid / 10;
        const int j  = tid - ch * 10;
        const float v = (j < 9) ? w[ch * 9 + j] : b[ch];
        const __half h = __float2half_rn(v);
        const uint16_t hb = __half_as_ushort(h);
        sWH[ch][j] = (uint32_t)hb | ((uint32_t)hb << 16);
    }
    __syncthreads();

    const int n  = blockIdx.z;
    const int pw = blockIdx.x * TX + tx;   // 0..255
    const int ph = blockIdx.y * TY + ty;   // 0..255
    if (pw >= POW || ph >= POW) return;

    // Direct global loads of the 4x4 fp32 patch (always in-bounds), then
    // convert to half2 rows: pr[r][0] = {h0,h1}, pr[r][1] = {h2,h3}.
    const float* __restrict__ px =
        x + ((size_t)n * INW + (size_t)(2 * ph)) * INW + 2 * pw;
    uint32_t pr[4][2];
    #pragma unroll
    for (int r = 0; r < 4; r++) {
        float2 a = *reinterpret_cast<const float2*>(px + r * INW);
        float2 c = *reinterpret_cast<const float2*>(px + r * INW + 2);
        pr[r][0] = h2_bits(__floats2half2_rn(a.x, a.y));
        pr[r][1] = h2_bits(__floats2half2_rn(c.x, c.y));
    }
    // Shifted pairs {h1,h2} per row (1 PRMT each). pairs[r][kx]:
    // kx=0 -> {h0,h1}, kx=1 -> {h1,h2}, kx=2 -> {h2,h3}.
    uint32_t pairs[4][3];
    #pragma unroll
    for (int r = 0; r < 4; r++) {
        pairs[r][0] = pr[r][0];
        pairs[r][1] = prmt5432(pr[r][0], pr[r][1]);
        pairs[r][2] = pr[r][1];
    }

    const int cstride = POW * POW;           // 32-bit indexing OK
    int o0 = ((n * 5) * POW + ph) * POW + pw;

    #pragma unroll
    for (int ch = 0; ch < 5; ch++) {
        // Vectorized weight fetch: 2x LDS.128 + 1x LDS.64 (channel-aligned).
        uint4 wa = *reinterpret_cast<const uint4*>(&sWH[ch][0]);   // taps 0-3
        uint4 wb = *reinterpret_cast<const uint4*>(&sWH[ch][4]);   // taps 4-7
        uint2 wc = *reinterpret_cast<const uint2*>(&sWH[ch][8]);   // tap8,bias
        const __half2 k0 = bits_h2(wa.x), k1 = bits_h2(wa.y);
        const __half2 k2 = bits_h2(wa.z), k3 = bits_h2(wa.w);
        const __half2 k4 = bits_h2(wb.x), k5 = bits_h2(wb.y);
        const __half2 k6 = bits_h2(wb.z), k7 = bits_h2(wb.w);
        const __half2 k8 = bits_h2(wc.x);
        const __half2 bias2 = bits_h2(wc.y);

        // acc0: conv row pair dy=0 (lanes = dx 0,1); acc1: dy=1.
        __half2 acc0 = bias2, acc1 = bias2;
        // ky = 0
        acc0 = __hfma2(bits_h2(pairs[0][0]), k0, acc0);
        acc1 = __hfma2(bits_h2(pairs[1][0]), k0, acc1);
        acc0 = __hfma2(bits_h2(pairs[0][1]), k1, acc0);
        acc1 = __hfma2(bits_h2(pairs[1][1]), k1, acc1);
        acc0 = __hfma2(bits_h2(pairs[0][2]), k2, acc0);
        acc1 = __hfma2(bits_h2(pairs[1][2]), k2, acc1);
        // ky = 1
        acc0 = __hfma2(bits_h2(pairs[1][0]), k3, acc0);
        acc1 = __hfma2(bits_h2(pairs[2][0]), k3, acc1);
        acc0 = __hfma2(bits_h2(pairs[1][1]), k4, acc0);
        acc1 = __hfma2(bits_h2(pairs[2][1]), k4, acc1);
        acc0 = __hfma2(bits_h2(pairs[1][2]), k5, acc0);
        acc1 = __hfma2(bits_h2(pairs[2][2]), k5, acc1);
        // ky = 2
        acc0 = __hfma2(bits_h2(pairs[2][0]), k6, acc0);
        acc1 = __hfma2(bits_h2(pairs[3][0]), k6, acc1);
        acc0 = __hfma2(bits_h2(pairs[2][1]), k7, acc0);
        acc1 = __hfma2(bits_h2(pairs[3][1]), k7, acc1);
        acc0 = __hfma2(bits_h2(pairs[2][2]), k8, acc0);
        acc1 = __hfma2(bits_h2(pairs[3][2]), k8, acc1);

        // Pool: vertical max in half2, then horizontal across lanes in fp32.
        const __half2 m2 = __hmax2(acc0, acc1);
        const float lo = __low2float(m2);
        const float hi = __high2float(m2);
        out[o0] = fmaxf(fmaxf(lo, hi), 0.0f);
        o0 += cstride;
    }
}

extern "C" void kernel_launch(void* const* d_in, const int* in_sizes, int n_in,
                              void* d_out, int out_size)
{
    const float* x = (const float*)d_in[0];
    const float* w = (const float*)d_in[1];
    const float* b = (const float*)d_in[2];
    float* out = (float*)d_out;

    dim3 block(TX, TY, 1);                       // 256 threads
    dim3 grid((POW + TX - 1) / TX,               // 8
              (POW + TY - 1) / TY,               // 32
              64);                               // batch
    fused_conv_bias_pool_relu_h2<<<grid, block>>>(x, w, b, out);
}